// round 14
// baseline (speedup 1.0000x reference)
#include <cuda_runtime.h>
#include <math.h>

#define THREADS     256
#define STAGES      5
#define TILE_BYTES  8192
#define TILE_CHUNKS 512                 // float4 chunks per tile
#define DEPTH       4                   // tiles in flight

__device__ __forceinline__ void mbar_init(unsigned mbar, unsigned count) {
    asm volatile("mbarrier.init.shared.b64 [%0], %1;" :: "r"(mbar), "r"(count) : "memory");
}
__device__ __forceinline__ void mbar_expect_tx(unsigned mbar, unsigned bytes) {
    asm volatile("mbarrier.arrive.expect_tx.shared.b64 _, [%0], %1;"
                 :: "r"(mbar), "r"(bytes) : "memory");
}
__device__ __forceinline__ void tma_bulk_g2s(unsigned smem_dst, const void* gsrc,
                                             unsigned bytes, unsigned mbar) {
    asm volatile("cp.async.bulk.shared::cta.global.mbarrier::complete_tx::bytes "
                 "[%0], [%1], %2, [%3];"
                 :: "r"(smem_dst), "l"(gsrc), "r"(bytes), "r"(mbar) : "memory");
}
__device__ __forceinline__ void mbar_wait_parity(unsigned mbar, unsigned parity) {
    asm volatile(
        "{\n\t"
        ".reg .pred P;\n\t"
        "WAIT_%=:\n\t"
        "mbarrier.try_wait.parity.acquire.cta.shared::cta.b64 P, [%0], %1, 0x989680;\n\t"
        "@P bra.uni DONE_%=;\n\t"
        "bra.uni WAIT_%=;\n\t"
        "DONE_%=:\n\t"
        "}"
        :: "r"(mbar), "r"(parity) : "memory");
}

__global__ __launch_bounds__(THREADS)
void wrpl_row_kernel(const float* __restrict__ scores,
                     const int* __restrict__ targets,
                     float* __restrict__ out,
                     int B, int C)
{
    __shared__ __align__(128) float4 buf[STAGES][TILE_CHUNKS];   // 40 KB
    __shared__ __align__(8) unsigned long long mbar_store[STAGES];
    __shared__ int   sh_rk [THREADS / 32];
    __shared__ int   sh_pos[THREADS / 32];
    __shared__ float sh_xs [THREADS / 32];

    const int row = blockIdx.x;
    const float* s = scores + (size_t)row * (size_t)C;
    const int t  = targets[row];
    const int td = threadIdx.x;

    const float gt  = __ldg(s + t);
    const float thr = gt - 1.0f;                 // hinge: l > 0 <=> x > gt-1
    const float gtb = nextafterf(gt, -__int_as_float(0x7f800000)); // x>gtb <=> x>=gt

    const int nChunks  = C >> 2;                 // C % 4 == 0
    const int rowBytes = C * 4;
    const int nTiles   = (rowBytes + TILE_BYTES - 1) / TILE_BYTES;
    const int tb       = t >> 2;                 // chunk containing j == t

    const unsigned mbar0 = (unsigned)__cvta_generic_to_shared(&mbar_store[0]);
    const unsigned sbuf0 = (unsigned)__cvta_generic_to_shared(&buf[0][0]);
    const char* gbase = (const char*)s;

    // ---- init mbarriers ----
    if (td == 0) {
        #pragma unroll
        for (int i = 0; i < STAGES; ++i)
            mbar_init(mbar0 + 8u * i, 1u);
    }
    __syncthreads();

    // ---- prologue: issue DEPTH tiles ----
    if (td == 0) {
        #pragma unroll
        for (int pt = 0; pt < DEPTH; ++pt) {
            if (pt < nTiles) {
                const int      off   = pt * TILE_BYTES;
                const unsigned bytes = (unsigned)min(TILE_BYTES, rowBytes - off);
                const unsigned mb    = mbar0 + 8u * pt;
                mbar_expect_tx(mb, bytes);
                tma_bulk_g2s(sbuf0 + (unsigned)pt * TILE_BYTES, gbase + off, bytes, mb);
            }
        }
    }

    int   cnt_rank = 0;
    int   cnt_pos  = 0;
    float xsum     = 0.0f;

#define PROC4(vv, thv)                                                          \
    { float x = (vv).x; cnt_rank += (x > (thv)); bool p = (x > thr); cnt_pos += p; if (p) xsum += x; } \
    { float x = (vv).y; cnt_rank += (x > (thv)); bool p = (x > thr); cnt_pos += p; if (p) xsum += x; } \
    { float x = (vv).z; cnt_rank += (x > (thv)); bool p = (x > thr); cnt_pos += p; if (p) xsum += x; } \
    { float x = (vv).w; cnt_rank += (x > (thv)); bool p = (x > thr); cnt_pos += p; if (p) xsum += x; }

    // ---- streaming loop over tiles ----
    for (int tile = 0; tile < nTiles; ++tile) {
        const int st = tile % STAGES;
        const unsigned ph = (unsigned)((tile / STAGES) & 1);
        mbar_wait_parity(mbar0 + 8u * st, ph);   // tile data visible (acquire)

        // consume: 2 float4 per thread
        #pragma unroll
        for (int k = 0; k < 2; ++k) {
            const int c4 = tile * TILE_CHUNKS + k * THREADS + td;
            if (c4 < nChunks) {
                const float th = (c4 <= tb) ? gtb : gt;
                float4 v = buf[st][k * THREADS + td];
                PROC4(v, th)
            }
        }
        __syncthreads();                         // stage fully consumed

        const int it = tile + DEPTH;
        if (td == 0 && it < nTiles) {
            const int      sb    = it % STAGES;
            const int      off   = it * TILE_BYTES;
            const unsigned bytes = (unsigned)min(TILE_BYTES, rowBytes - off);
            const unsigned mb    = mbar0 + 8u * sb;
            mbar_expect_tx(mb, bytes);
            tma_bulk_g2s(sbuf0 + (unsigned)sb * TILE_BYTES, gbase + off, bytes, mb);
        }
    }
#undef PROC4

    // ---- exact correction for the boundary chunk (thread 0) ----
    //   idx == t          : rank -= 1, pos -= 1, xsum -= gt
    //   idx  > t, x == gt : rank -= 1  (counted under GE, should be GT)
    if (td == 0) {
        const int base = tb << 2;
        #pragma unroll
        for (int e = 0; e < 4; ++e) {
            const int idx = base + e;
            const float x = __ldg(s + idx);
            if (idx == t) {
                cnt_rank -= 1;
                cnt_pos  -= 1;
                xsum     -= gt;
            } else if (idx > t && x == gt) {
                cnt_rank -= 1;
            }
        }
    }

    // ---- block reduction ----
    const unsigned FULL = 0xFFFFFFFFu;
    #pragma unroll
    for (int off = 16; off > 0; off >>= 1) {
        cnt_rank += __shfl_down_sync(FULL, cnt_rank, off);
        cnt_pos  += __shfl_down_sync(FULL, cnt_pos,  off);
        xsum     += __shfl_down_sync(FULL, xsum,     off);
    }

    const int lane = td & 31;
    const int wid  = td >> 5;
    if (lane == 0) {
        sh_rk[wid]  = cnt_rank;
        sh_pos[wid] = cnt_pos;
        sh_xs[wid]  = xsum;
    }
    __syncthreads();

    if (td == 0) {
        int   rk = 0, p = 0;
        float xs = 0.0f;
        #pragma unroll
        for (int i = 0; i < THREADS / 32; i++) {
            rk += sh_rk[i]; p += sh_pos[i]; xs += sh_xs[i];
        }

        const int rank = rk + 1;
        const float hinge = xs - (float)p * thr;

        // harmonic number H(rank)
        double H;
        if (rank <= 64) {
            H = 0.0;
            for (int i = 1; i <= rank; i++) H += 1.0 / (double)i;
        } else {
            double n  = (double)rank;
            double n2 = n * n;
            H = log(n) + 0.57721566490153286
              + 1.0 / (2.0 * n) - 1.0 / (12.0 * n2) + 1.0 / (120.0 * n2 * n2);
        }

        float npos = (float)p + 1e-7f;
        float loss = (float)H / npos * hinge;
        atomicAdd(out, loss / (float)B);
    }
}

extern "C" void kernel_launch(void* const* d_in, const int* in_sizes, int n_in,
                              void* d_out, int out_size)
{
    const float* scores  = (const float*)d_in[0];
    const int*   targets = (const int*)d_in[1];
    float*       out     = (float*)d_out;

    const int B = in_sizes[1];
    const int C = in_sizes[0] / B;

    cudaMemsetAsync(out, 0, sizeof(float));
    wrpl_row_kernel<<<B, THREADS>>>(scores, targets, out, B, C);
}

// round 15
// speedup vs baseline: 1.0941x; 1.0941x over previous
#include <cuda_runtime.h>
#include <math.h>

#define THREADS 256
#define STAGES  8u                      // power of 2: ring index is an AND
#define CPT     THREADS                 // chunks (16B) per tile = 1 per thread

__device__ __forceinline__ void cp_async16(void* smem_dst, const void* gsrc) {
    unsigned saddr = (unsigned)__cvta_generic_to_shared(smem_dst);
    asm volatile("cp.async.cg.shared.global [%0], [%1], 16;\n"
                 :: "r"(saddr), "l"(gsrc));
}
__device__ __forceinline__ void cp_async_commit() {
    asm volatile("cp.async.commit_group;\n" ::: "memory");
}
template<int N>
__device__ __forceinline__ void cp_async_wait() {
    asm volatile("cp.async.wait_group %0;\n" :: "n"(N) : "memory");
}

__global__ __launch_bounds__(THREADS)
void wrpl_row_kernel(const float* __restrict__ scores,
                     const int* __restrict__ targets,
                     float* __restrict__ out,
                     int B, int C)
{
    // Each thread owns one 16B slot per stage -> no cross-thread smem sharing,
    // no __syncthreads in the streaming loop. wait_group orders own write/read.
    __shared__ float4 buf[STAGES][CPT];          // 32 KB

    const int row = blockIdx.x;
    const float* s = scores + (size_t)row * (size_t)C;
    const int t = targets[row];

    const float gt  = __ldg(s + t);
    const float thr = gt - 1.0f;        // l > 0  <=>  s > gt - 1

    const unsigned nChunks = (unsigned)(C >> 2); // float4 chunks per row (C % 4 == 0)
    const unsigned nTiles  = (nChunks + CPT - 1u) / CPT;
    const int      tb      = t >> 2;    // chunk containing the target

    const float4* s4 = reinterpret_cast<const float4*>(s);
    const unsigned td = threadIdx.x;

    int   cnt_rank = 0;   // #{j<t: s_j >= gt} + #{j>t: s_j > gt} = rank-1
    int   cnt_pos  = 0;   // #{j != t : s_j > thr}
    float xsum     = 0.0f;

    // ---- prologue: fill STAGES-2 stages ----
    #pragma unroll
    for (unsigned pt = 0; pt < STAGES - 2u; ++pt) {
        unsigned c4 = pt * CPT + td;
        if (pt < nTiles && c4 < nChunks)
            cp_async16(&buf[pt][td], s4 + c4);
        cp_async_commit();
    }

#define PROC_GE(xv) { float x = (xv); cnt_rank += (x >= gt); bool p = (x > thr); cnt_pos += p; if (p) xsum += x; }
#define PROC_GT(xv) { float x = (xv); cnt_rank += (x >  gt); bool p = (x > thr); cnt_pos += p; if (p) xsum += x; }

    // ---- streaming loop: 1 issue + 1 wait per tile, no barriers ----
    for (unsigned tile = 0; tile < nTiles; ++tile) {
        const unsigned it = tile + STAGES - 2u;
        if (it < nTiles) {
            unsigned c4i = it * CPT + td;
            if (c4i < nChunks)
                cp_async16(&buf[it & (STAGES - 1u)][td], s4 + c4i);
        }
        cp_async_commit();
        cp_async_wait<(int)(STAGES - 2u)>();     // own tile `tile` is complete

        const int c4 = (int)(tile * CPT + td);
        if (c4 < (int)nChunks) {
            float4 v = buf[tile & (STAGES - 1u)][td];
            if (c4 < tb) {               // all idx < t
                PROC_GE(v.x) PROC_GE(v.y) PROC_GE(v.z) PROC_GE(v.w)
            } else if (c4 > tb) {        // all idx > t
                PROC_GT(v.x) PROC_GT(v.y) PROC_GT(v.z) PROC_GT(v.w)
            } else {                     // boundary chunk: contains j == t
                const float xv[4] = {v.x, v.y, v.z, v.w};
                const int base = c4 << 2;
                #pragma unroll
                for (int e = 0; e < 4; ++e) {
                    int idx = base + e;
                    if (idx == t) continue;
                    float x = xv[e];
                    cnt_rank += (idx < t) ? (x >= gt) : (x > gt);
                    bool p = (x > thr);
                    cnt_pos += p;
                    if (p) xsum += x;
                }
            }
        }
    }
#undef PROC_GE
#undef PROC_GT

    // ---- block reduction ----
    const unsigned FULL = 0xFFFFFFFFu;
    #pragma unroll
    for (int off = 16; off > 0; off >>= 1) {
        cnt_rank += __shfl_down_sync(FULL, cnt_rank, off);
        cnt_pos  += __shfl_down_sync(FULL, cnt_pos,  off);
        xsum     += __shfl_down_sync(FULL, xsum,     off);
    }

    __shared__ int   sh_rk [THREADS / 32];
    __shared__ int   sh_pos[THREADS / 32];
    __shared__ float sh_xs [THREADS / 32];

    const unsigned lane = td & 31u;
    const unsigned wid  = td >> 5;
    if (lane == 0) {
        sh_rk[wid]  = cnt_rank;
        sh_pos[wid] = cnt_pos;
        sh_xs[wid]  = xsum;
    }
    __syncthreads();

    if (td == 0) {
        int   rk = 0, p = 0;
        float xs = 0.0f;
        #pragma unroll
        for (int i = 0; i < THREADS / 32; i++) {
            rk += sh_rk[i]; p += sh_pos[i]; xs += sh_xs[i];
        }

        const int rank = rk + 1;
        const float hinge = xs - (float)p * thr;

        // harmonic number H(rank)
        double H;
        if (rank <= 64) {
            H = 0.0;
            for (int i = 1; i <= rank; i++) H += 1.0 / (double)i;
        } else {
            double n  = (double)rank;
            double n2 = n * n;
            H = log(n) + 0.57721566490153286
              + 1.0 / (2.0 * n) - 1.0 / (12.0 * n2) + 1.0 / (120.0 * n2 * n2);
        }

        float npos = (float)p + 1e-7f;
        float loss = (float)H / npos * hinge;
        atomicAdd(out, loss / (float)B);
    }
}

extern "C" void kernel_launch(void* const* d_in, const int* in_sizes, int n_in,
                              void* d_out, int out_size)
{
    const float* scores  = (const float*)d_in[0];
    const int*   targets = (const int*)d_in[1];
    float*       out     = (float*)d_out;

    const int B = in_sizes[1];
    const int C = in_sizes[0] / B;

    // graph memset node: cheaper than a zeroing kernel launch
    cudaMemsetAsync(out, 0, sizeof(float));
    wrpl_row_kernel<<<B, THREADS>>>(scores, targets, out, B, C);
}

// round 16
// speedup vs baseline: 1.1014x; 1.0066x over previous
#include <cuda_runtime.h>
#include <math.h>

#define THREADS 256
#define STAGES  8u                      // power of 2: ring index is an AND
#define DEPTH   7u                      // tiles in flight (max for 8-stage ring)
#define CPT     THREADS                 // chunks (16B) per tile = 1 per thread

__device__ __forceinline__ void cp_async16(void* smem_dst, const void* gsrc) {
    unsigned saddr = (unsigned)__cvta_generic_to_shared(smem_dst);
    asm volatile("cp.async.cg.shared.global [%0], [%1], 16;\n"
                 :: "r"(saddr), "l"(gsrc));
}
__device__ __forceinline__ void cp_async_commit() {
    asm volatile("cp.async.commit_group;\n" ::: "memory");
}
template<int N>
__device__ __forceinline__ void cp_async_wait() {
    asm volatile("cp.async.wait_group %0;\n" :: "n"(N) : "memory");
}

__global__ __launch_bounds__(THREADS)
void wrpl_row_kernel(const float* __restrict__ scores,
                     const int* __restrict__ targets,
                     float* __restrict__ out,
                     int B, int C)
{
    // Each thread owns one 16B slot per stage -> no cross-thread smem sharing,
    // no __syncthreads in the streaming loop. wait_group orders own write/read.
    __shared__ float4 buf[STAGES][CPT];          // 32 KB

    const int row = blockIdx.x;
    const float* s = scores + (size_t)row * (size_t)C;
    const int t = targets[row];

    const float gt  = __ldg(s + t);
    const float thr = gt - 1.0f;        // l > 0  <=>  s > gt - 1

    const unsigned nChunks = (unsigned)(C >> 2); // float4 chunks per row (C % 4 == 0)
    const unsigned nTiles  = (nChunks + CPT - 1u) / CPT;
    const int      tb      = t >> 2;    // chunk containing the target

    const float4* s4 = reinterpret_cast<const float4*>(s);
    const unsigned td = threadIdx.x;

    int   cnt_rank = 0;   // #{j<t: s_j >= gt} + #{j>t: s_j > gt} = rank-1
    int   cnt_pos  = 0;   // #{j != t : s_j > thr}
    float xsum     = 0.0f;

    // ---- prologue: fill DEPTH stages ----
    #pragma unroll
    for (unsigned pt = 0; pt < DEPTH; ++pt) {
        unsigned c4 = pt * CPT + td;
        if (pt < nTiles && c4 < nChunks)
            cp_async16(&buf[pt][td], s4 + c4);
        cp_async_commit();
    }

#define PROC_GE(xv) { float x = (xv); cnt_rank += (x >= gt); bool p = (x > thr); cnt_pos += p; if (p) xsum += x; }
#define PROC_GT(xv) { float x = (xv); cnt_rank += (x >  gt); bool p = (x > thr); cnt_pos += p; if (p) xsum += x; }

    // ---- streaming loop: 1 issue + 1 wait per tile, no barriers ----
    for (unsigned tile = 0; tile < nTiles; ++tile) {
        const unsigned it = tile + DEPTH;
        if (it < nTiles) {
            unsigned c4i = it * CPT + td;
            if (c4i < nChunks)
                cp_async16(&buf[it & (STAGES - 1u)][td], s4 + c4i);
        }
        cp_async_commit();
        cp_async_wait<(int)DEPTH>();             // own tile `tile` is complete

        const int c4 = (int)(tile * CPT + td);
        if (c4 < (int)nChunks) {
            float4 v = buf[tile & (STAGES - 1u)][td];
            if (c4 < tb) {               // all idx < t
                PROC_GE(v.x) PROC_GE(v.y) PROC_GE(v.z) PROC_GE(v.w)
            } else if (c4 > tb) {        // all idx > t
                PROC_GT(v.x) PROC_GT(v.y) PROC_GT(v.z) PROC_GT(v.w)
            } else {                     // boundary chunk: contains j == t
                const float xv[4] = {v.x, v.y, v.z, v.w};
                const int base = c4 << 2;
                #pragma unroll
                for (int e = 0; e < 4; ++e) {
                    int idx = base + e;
                    if (idx == t) continue;
                    float x = xv[e];
                    cnt_rank += (idx < t) ? (x >= gt) : (x > gt);
                    bool p = (x > thr);
                    cnt_pos += p;
                    if (p) xsum += x;
                }
            }
        }
    }
#undef PROC_GE
#undef PROC_GT

    // ---- block reduction ----
    const unsigned FULL = 0xFFFFFFFFu;
    #pragma unroll
    for (int off = 16; off > 0; off >>= 1) {
        cnt_rank += __shfl_down_sync(FULL, cnt_rank, off);
        cnt_pos  += __shfl_down_sync(FULL, cnt_pos,  off);
        xsum     += __shfl_down_sync(FULL, xsum,     off);
    }

    __shared__ int   sh_rk [THREADS / 32];
    __shared__ int   sh_pos[THREADS / 32];
    __shared__ float sh_xs [THREADS / 32];

    const unsigned lane = td & 31u;
    const unsigned wid  = td >> 5;
    if (lane == 0) {
        sh_rk[wid]  = cnt_rank;
        sh_pos[wid] = cnt_pos;
        sh_xs[wid]  = xsum;
    }
    __syncthreads();

    if (td == 0) {
        int   rk = 0, p = 0;
        float xs = 0.0f;
        #pragma unroll
        for (int i = 0; i < THREADS / 32; i++) {
            rk += sh_rk[i]; p += sh_pos[i]; xs += sh_xs[i];
        }

        const int rank = rk + 1;
        const float hinge = xs - (float)p * thr;

        // harmonic number H(rank)
        double H;
        if (rank <= 64) {
            H = 0.0;
            for (int i = 1; i <= rank; i++) H += 1.0 / (double)i;
        } else {
            double n  = (double)rank;
            double n2 = n * n;
            H = log(n) + 0.57721566490153286
              + 1.0 / (2.0 * n) - 1.0 / (12.0 * n2) + 1.0 / (120.0 * n2 * n2);
        }

        float npos = (float)p + 1e-7f;
        float loss = (float)H / npos * hinge;
        atomicAdd(out, loss / (float)B);
    }
}

extern "C" void kernel_launch(void* const* d_in, const int* in_sizes, int n_in,
                              void* d_out, int out_size)
{
    const float* scores  = (const float*)d_in[0];
    const int*   targets = (const int*)d_in[1];
    float*       out     = (float*)d_out;

    const int B = in_sizes[1];
    const int C = in_sizes[0] / B;

    // graph memset node: cheaper than a zeroing kernel launch
    cudaMemsetAsync(out, 0, sizeof(float));
    wrpl_row_kernel<<<B, THREADS>>>(scores, targets, out, B, C);
}